// round 11
// baseline (speedup 1.0000x reference)
#include <cuda_runtime.h>

// CTC forward loss. B=32, T=1000, V=1024, L=100, S=2L+1=201.
//
// Pass 1: g_emit[b][t][s] = pred[b][t][ext[s]] + EPS (linear; 0 if invalid).
// Pass 2: linear-domain DP, HALO-WINDOW wavefront: 4 steps per __syncthreads.
//   8 warps; warp w covers lanes 26w-6..26w+25 (6-lane halo). Step 1 reads
//   smem (all lanes valid), steps 2..4 use shfl_up (lose 2 bottom lanes/step),
//   net lanes r>=6 (26/warp, 208 total) write back. Exact 2^k block rescale
//   once per window (same 4-step cadence as R10), target 2^120, IEEE ops.
// Mean-reduce fused.

#define Bc 32
#define Tc 1000
#define Vc 1024
#define Lc 100
#define Sc 201
#define EPSV (1e-7f)
#define EMIT_NT 224
#define ESTR 224
#define DP_NT 256          // 8 warps
#define NWARP 8
#define KW 4               // steps per window
#define ASZ 216            // alpha idx = g + 8, g in [-8, 207]
#define LN2F 0.6931471805599453f

__device__ float    g_emit[(size_t)Bc * Tc * ESTR];   // ~28.7 MB scratch
__device__ float    g_loss[Bc];
__device__ unsigned g_done;                           // zero-init; atomicInc wraps

__device__ __forceinline__ float lg2f_(float x) { float y; asm("lg2.approx.ftz.f32 %0, %1;" : "=f"(y) : "f"(x)); return y; }

// ---------------- Pass 1: emission gather (parallel, linear) ----------------
__global__ __launch_bounds__(EMIT_NT)
void ctc_emit_kernel(const float* __restrict__ pred,
                     const int*   __restrict__ lenA,
                     const int*   __restrict__ lenB,
                     const int*   __restrict__ labels)
{
    const int t = blockIdx.x;
    const int b = blockIdx.y;
    const int s = threadIdx.x;

    const int la = lenA[b], lb = lenB[b];
    const int ilen = min(max(max(la, lb), 1), Tc);
    const int llen = min(max(min(la, lb), 1), Lc);
    if (t >= ilen) return;

    int ext = Vc - 1;
    if ((s & 1) && s < Sc) ext = labels[b * Lc + (s >> 1)] & (Vc - 1);

    const bool valid = (s < Sc) && (s < 2 * llen + 1);
    const float p = pred[((size_t)b * Tc + t) * Vc + ext];
    g_emit[((size_t)b * Tc + t) * ESTR + s] = valid ? (p + EPSV) : 0.0f;
}

// ---------------- Pass 2: halo-window DP (linear domain) ----------------
__global__ __launch_bounds__(DP_NT, 1)
void ctc_dp_kernel(const int* __restrict__ lenA,
                   const int* __restrict__ lenB,
                   const int* __restrict__ labels,
                   float*     __restrict__ out)
{
    __shared__ float    asm2[2][ASZ];     // alpha ping-pong, idx = g + 8
    __shared__ unsigned red[2][NWARP];    // per-window block-max slots

    const int b    = blockIdx.x;
    const int tid  = threadIdx.x;
    const int w    = tid >> 5;
    const int lane = tid & 31;
    const int g    = 26 * w + lane - 6;   // global lane, -6..207

    const int la = lenA[b], lb = lenB[b];
    const int ilen = min(max(max(la, lb), 1), Tc);
    const int llen = min(max(min(la, lb), 1), Lc);

    float allowf = 0.0f;
    if (g >= 1 && g < Sc && (g & 1)) {
        if (g == 1) allowf = 1.0f;
        else {
            const int e0 = labels[b * Lc + (g >> 1)] & (Vc - 1);
            allowf = (e0 != (labels[b * Lc + (g >> 1) - 1] & (Vc - 1))) ? 1.0f : 0.0f;
        }
    }

    const float  emask = (g >= 0) ? 1.0f : 0.0f;
    const float* eb = g_emit + (size_t)b * Tc * ESTR + max(g, 0);

    // init: zero both alpha buffers (pads included)
    if (tid < ASZ) { asm2[0][tid] = 0.0f; asm2[1][tid] = 0.0f; }
    __syncthreads();
    if (g == 0 || g == 1) asm2[0][g + 8] = eb[0];   // t = 0 (lanes 0,1 always valid)

    // prefetch emissions for steps 1..8 into double window buffer
    float er[2][KW];
    #pragma unroll
    for (int j = 0; j < KW; ++j) {
        int t1 = min(1 + j, Tc - 1);
        int t2 = min(1 + KW + j, Tc - 1);
        er[0][j] = eb[(size_t)t1 * ESTR] * emask;
        er[1][j] = eb[(size_t)t2 * ESTR] * emask;
    }
    __syncthreads();

    int   t = 1, p = 0, c = 0;
    int   Ktot = 0, kPend = 0;
    float pend1 = 1.0f, pend2 = 1.0f;
    bool  haveP = false;

    // ---- full windows: 4 steps per barrier ----
    while (t + KW <= ilen) {
        float a = asm2[p][g + 8];
        #pragma unroll
        for (int j = 0; j < KW; ++j) {
            float am1 = __shfl_up_sync(0xffffffffu, a, 1);
            float am2 = __shfl_up_sync(0xffffffffu, a, 2);
            if (j == 0 && lane < 2) {            // halo from smem (valid pre-window state)
                if (lane == 0) am1 = asm2[p][g + 7];
                am2 = asm2[p][g + 6];
            }
            float nv = __fmul_rn(__fmaf_rn(allowf, am2, __fadd_rn(a, am1)), er[c][j]);
            if (j == 0 && haveP) { nv = __fmul_rn(__fmul_rn(nv, pend1), pend2); Ktot += kPend; }
            a = nv;

            // prefetch emission for step t + 8 + j (next-next window)
            int tn = t + 2 * KW + j; if (tn > Tc - 1) tn = Tc - 1;
            er[c][j] = eb[(size_t)tn * ESTR] * emask;
        }

        // writeback net lanes + block max (values >= 0: uint order == float order)
        if (lane >= 2 * (KW - 1)) asm2[p ^ 1][g + 8] = a;
        unsigned mv = (lane >= 2 * (KW - 1)) ? __float_as_uint(a) : 0u;
        mv = __reduce_max_sync(0xffffffffu, mv);
        if (lane == 0) red[p][w] = mv;
        __syncthreads();

        unsigned M = red[p][0];
        #pragma unroll
        for (int ww = 1; ww < NWARP; ++ww) M = max(M, red[p][ww]);
        const int ee = (int)((M >> 23) & 0xFFu);
        kPend = 247 - ee;                          // rescale target 2^120
        const int k1 = kPend >> 1;
        pend1 = __uint_as_float((unsigned)(127 + k1) << 23);
        pend2 = __uint_as_float((unsigned)(127 + (kPend - k1)) << 23);
        haveP = true;

        p ^= 1; c ^= 1; t += KW;
    }

    // ---- tail (< 4 steps); emissions already in er[c] ----
    const int rem = ilen - t;
    if (rem > 0) {
        float a = asm2[p][g + 8];
        for (int j = 0; j < rem; ++j) {
            float am1 = __shfl_up_sync(0xffffffffu, a, 1);
            float am2 = __shfl_up_sync(0xffffffffu, a, 2);
            if (j == 0 && lane < 2) {
                if (lane == 0) am1 = asm2[p][g + 7];
                am2 = asm2[p][g + 6];
            }
            float nv = __fmul_rn(__fmaf_rn(allowf, am2, __fadd_rn(a, am1)), er[c][j]);
            if (j == 0 && haveP) { nv = __fmul_rn(__fmul_rn(nv, pend1), pend2); Ktot += kPend; }
            a = nv;
        }
        if (lane >= 2 * (KW - 1)) asm2[p ^ 1][g + 8] = a;
        __syncthreads();
        p ^= 1;
    }

    // ---- finalize: loglik = (log2(a1+a2) - Ktot) * ln2; fused mean ----
    if (tid == 0) {
        const float a1 = asm2[p][2 * llen - 1 + 8];
        const float a2 = asm2[p][2 * llen + 8];
        const float ll = (lg2f_(__fadd_rn(a1, a2)) - (float)Ktot) * LN2F;
        g_loss[b] = -ll;

        __threadfence();
        const unsigned old = atomicInc(&g_done, Bc - 1);
        if (old == Bc - 1) {
            __threadfence();
            float acc = 0.0f;
            #pragma unroll
            for (int i = 0; i < Bc; ++i) acc += g_loss[i];
            out[0] = acc * (1.0f / (float)Bc);
        }
    }
}

extern "C" void kernel_launch(void* const* d_in, const int* in_sizes, int n_in,
                              void* d_out, int out_size)
{
    // Identify inputs by size rank (robust to ordering / bytes-vs-elems).
    int idx[4] = {0, 1, 2, 3};
    for (int i = 0; i < 3; ++i)
        for (int j = i + 1; j < 4; ++j)
            if ((long long)in_sizes[idx[j]] > (long long)in_sizes[idx[i]]) {
                int tmp = idx[i]; idx[i] = idx[j]; idx[j] = tmp;
            }

    const float* pred   = (const float*)d_in[idx[0]];  // [B,T,V]
    const int*   labels = (const int*)  d_in[idx[1]];  // [B,L]
    const int*   lenA   = (const int*)  d_in[idx[2]];  // length vectors
    const int*   lenB   = (const int*)  d_in[idx[3]];

    float* out = (float*)d_out;

    dim3 g1(Tc, Bc);
    ctc_emit_kernel<<<g1, EMIT_NT>>>(pred, lenA, lenB, labels);
    ctc_dp_kernel<<<Bc, DP_NT>>>(lenA, lenB, labels, out);
}

// round 12
// speedup vs baseline: 1.1437x; 1.1437x over previous
#include <cuda_runtime.h>

// CTC forward loss. B=32, T=1000, V=1024, L=100, S=2L+1=201.
//
// Pass 1: g_emit[b][t][s] = pred[b][t][ext[s]] + EPS (linear; 0 if invalid).
// Pass 2: linear-domain DP, 2 STEPS PER BARRIER via redundant neighbor
//   recompute through SHARED MEMORY (no shfl -- R11 lesson). Thread s loads
//   alpha[s..s-4], recomputes step-t nodes at s, s-1, s-2, then step t+1 at s.
//   Exact 2^k block rescale every 2 windows (4-step cadence, target 2^120),
//   IEEE ops (denormal-preserving). Mean-reduce fused.

#define Bc 32
#define Tc 1000
#define Vc 1024
#define Lc 100
#define Sc 201
#define EPSV (1e-7f)
#define NTHREADS 224
#define ESTR 224
#define ASZ (NTHREADS + 8)    // lane s at [s+4]; [0..3] zero pad
#define LN2F 0.6931471805599453f

__device__ float    g_emit[(size_t)Bc * Tc * ESTR];   // ~28.7 MB scratch
__device__ float    g_loss[Bc];
__device__ unsigned g_done;                           // zero-init; atomicInc wraps

__device__ __forceinline__ float lg2f_(float x) { float y; asm("lg2.approx.ftz.f32 %0, %1;" : "=f"(y) : "f"(x)); return y; }

// ---------------- Pass 1: emission gather (parallel, linear) ----------------
__global__ __launch_bounds__(NTHREADS)
void ctc_emit_kernel(const float* __restrict__ pred,
                     const int*   __restrict__ lenA,
                     const int*   __restrict__ lenB,
                     const int*   __restrict__ labels)
{
    const int t = blockIdx.x;
    const int b = blockIdx.y;
    const int s = threadIdx.x;

    const int la = lenA[b], lb = lenB[b];
    const int ilen = min(max(max(la, lb), 1), Tc);
    const int llen = min(max(min(la, lb), 1), Lc);
    if (t >= ilen) return;

    int ext = Vc - 1;
    if ((s & 1) && s < Sc) ext = labels[b * Lc + (s >> 1)] & (Vc - 1);

    const bool valid = (s < Sc) && (s < 2 * llen + 1);
    const float p = pred[((size_t)b * Tc + t) * Vc + ext];
    g_emit[((size_t)b * Tc + t) * ESTR + s] = valid ? (p + EPSV) : 0.0f;
}

// allow-skip coefficient for extended lane x (1.0 iff odd, labels differ)
__device__ __forceinline__ float allow_at(int x, const int* lab, int b)
{
    if (x < 1 || x >= Sc || !(x & 1)) return 0.0f;
    if (x == 1) return 1.0f;
    const int e0 = lab[b * Lc + (x >> 1)]     & (Vc - 1);
    const int e1 = lab[b * Lc + (x >> 1) - 1] & (Vc - 1);
    return (e0 != e1) ? 1.0f : 0.0f;
}

// ---------------- Pass 2: serial DP, 2 steps per barrier ----------------
__global__ __launch_bounds__(NTHREADS, 1)
void ctc_dp_kernel(const int* __restrict__ lenA,
                   const int* __restrict__ lenB,
                   const int* __restrict__ labels,
                   float*     __restrict__ out)
{
    __shared__ float    alpha[2][ASZ];
    __shared__ unsigned red[7];

    const int b = blockIdx.x;
    const int s = threadIdx.x;

    const int la = lenA[b], lb = lenB[b];
    const int ilen = min(max(max(la, lb), 1), Tc);
    const int llen = min(max(min(la, lb), 1), Lc);

    // allow coefficients at s, s-1, s-2 (constants for the whole run)
    const float al0 = allow_at(s,     labels, b);
    const float al1 = allow_at(s - 1, labels, b);
    const float al2 = allow_at(s - 2, labels, b);

    const float* ebs  = g_emit + (size_t)b * Tc * ESTR + s;
    const float* ebs1 = g_emit + (size_t)b * Tc * ESTR + max(s - 1, 0);
    const float* ebs2 = g_emit + (size_t)b * Tc * ESTR + max(s - 2, 0);
    // (clamped cols feed nodes whose alpha inputs are all 0 -> product is 0)

    // zero both buffers (pads included)
    alpha[0][s] = 0.0f;  alpha[1][s] = 0.0f;
    if (s < ASZ - NTHREADS) {
        alpha[0][NTHREADS + s] = 0.0f;
        alpha[1][NTHREADS + s] = 0.0f;
    }
    __syncthreads();

    // ---- t = 0 (emit pass already zeroed invalid lanes) ----
    alpha[0][s + 4] = (s < 2) ? ebs[0] : 0.0f;

    // ---- preload 2 windows of emissions ----
    // er[c][0]=e(t,s)  er[c][1]=e(t+1,s)  er[c][2]=e(t,s-1)  er[c][3]=e(t,s-2)
    float er[2][4];
    #pragma unroll
    for (int c2 = 0; c2 < 2; ++c2) {
        const int tw = 1 + 2 * c2;
        const int t0 = min(tw,     Tc - 1);
        const int t1 = min(tw + 1, Tc - 1);
        er[c2][0] = ebs [(size_t)t0 * ESTR];
        er[c2][1] = ebs [(size_t)t1 * ESTR];
        er[c2][2] = ebs1[(size_t)t0 * ESTR];
        er[c2][3] = ebs2[(size_t)t0 * ESTR];
    }
    __syncthreads();

    int   t = 1, cur = 0, c = 0, wi = 0;
    int   Ktot = 0, kPend = 0;
    float pend1 = 1.0f, pend2 = 1.0f;
    bool  haveP = false;

    // ---- full windows: steps t, t+1 (both <= ilen-1) ----
    while (t + 1 < ilen) {
        const float a0 = alpha[cur][s + 4];
        const float a1 = alpha[cur][s + 3];
        const float a2 = alpha[cur][s + 2];
        const float a3 = alpha[cur][s + 1];
        const float a4 = alpha[cur][s + 0];

        // step t nodes at lanes s, s-1, s-2 (bit-identical to those lanes' own math)
        const float A0 = __fmul_rn(__fmaf_rn(al0, a2, __fadd_rn(a0, a1)), er[c][0]);
        const float A1 = __fmul_rn(__fmaf_rn(al1, a3, __fadd_rn(a1, a2)), er[c][2]);
        const float A2 = __fmul_rn(__fmaf_rn(al2, a4, __fadd_rn(a2, a3)), er[c][3]);
        // step t+1 at lane s
        float nv = __fmul_rn(__fmaf_rn(al0, A2, __fadd_rn(A0, A1)), er[c][1]);
        if (haveP) { nv = __fmul_rn(__fmul_rn(nv, pend1), pend2); Ktot += kPend; haveP = false; }

        // prefetch window t+4 into the just-consumed slots
        {
            const int t0 = min(t + 4, Tc - 1);
            const int t1 = min(t + 5, Tc - 1);
            er[c][0] = ebs [(size_t)t0 * ESTR];
            er[c][1] = ebs [(size_t)t1 * ESTR];
            er[c][2] = ebs1[(size_t)t0 * ESTR];
            er[c][3] = ebs2[(size_t)t0 * ESTR];
        }

        alpha[cur ^ 1][s + 4] = nv;

        if (wi & 1) {   // block max (nv >= 0: uint order == float order)
            const unsigned mv = __reduce_max_sync(0xffffffffu, __float_as_uint(nv));
            if ((s & 31) == 0) red[s >> 5] = mv;
        }
        __syncthreads();
        if (wi & 1) {
            unsigned M = red[0];
            #pragma unroll
            for (int ww = 1; ww < 7; ++ww) M = max(M, red[ww]);
            const int ee = (int)((M >> 23) & 0xFFu);
            kPend = 247 - ee;                       // rescale target 2^120
            const int k1 = kPend >> 1;
            pend1 = __uint_as_float((unsigned)(127 + k1) << 23);
            pend2 = __uint_as_float((unsigned)(127 + (kPend - k1)) << 23);
            haveP = true;
        }

        cur ^= 1; c ^= 1; ++wi; t += 2;
    }

    // ---- tail: one leftover step (er[c][0] = e(t,s)) ----
    if (t < ilen) {
        const float a0 = alpha[cur][s + 4];
        const float a1 = alpha[cur][s + 3];
        const float a2 = alpha[cur][s + 2];
        float nv = __fmul_rn(__fmaf_rn(al0, a2, __fadd_rn(a0, a1)), er[c][0]);
        if (haveP) { nv = __fmul_rn(__fmul_rn(nv, pend1), pend2); Ktot += kPend; haveP = false; }
        alpha[cur ^ 1][s + 4] = nv;
        __syncthreads();
        cur ^= 1;
    }

    // ---- finalize (pending-but-unapplied rescale cancels: ignore it) ----
    if (s == 0) {
        const float a1f = alpha[cur][2 * llen - 1 + 4];
        const float a2f = alpha[cur][2 * llen + 4];
        const float ll  = (lg2f_(__fadd_rn(a1f, a2f)) - (float)Ktot) * LN2F;
        g_loss[b] = -ll;

        __threadfence();
        const unsigned old = atomicInc(&g_done, Bc - 1);
        if (old == Bc - 1) {
            __threadfence();
            float acc = 0.0f;
            #pragma unroll
            for (int i = 0; i < Bc; ++i) acc += g_loss[i];
            out[0] = acc * (1.0f / (float)Bc);
        }
    }
}

extern "C" void kernel_launch(void* const* d_in, const int* in_sizes, int n_in,
                              void* d_out, int out_size)
{
    // Identify inputs by size rank (robust to ordering / bytes-vs-elems).
    int idx[4] = {0, 1, 2, 3};
    for (int i = 0; i < 3; ++i)
        for (int j = i + 1; j < 4; ++j)
            if ((long long)in_sizes[idx[j]] > (long long)in_sizes[idx[i]]) {
                int tmp = idx[i]; idx[i] = idx[j]; idx[j] = tmp;
            }

    const float* pred   = (const float*)d_in[idx[0]];  // [B,T,V]
    const int*   labels = (const int*)  d_in[idx[1]];  // [B,L]
    const int*   lenA   = (const int*)  d_in[idx[2]];  // length vectors
    const int*   lenB   = (const int*)  d_in[idx[3]];

    float* out = (float*)d_out;

    dim3 g1(Tc, Bc);
    ctc_emit_kernel<<<g1, NTHREADS>>>(pred, lenA, lenB, labels);
    ctc_dp_kernel<<<Bc, NTHREADS>>>(lenA, lenB, labels, out);
}